// round 1
// baseline (speedup 1.0000x reference)
#include <cuda_runtime.h>

#define SEQ   2048
#define H     128
#define B     64
#define OUTF  512
#define NREC  64
#define NFC   84        // 4 col-blocks x 21 CTAs; grid = 148 (wave-1 co-resident, no deadlock)
#define THREADS 384

// Scratch: hidden-state history + per-batch progress watermark (device globals; no allocs)
__device__ float g_hs[(size_t)B * SEQ * H];
__device__ int   g_wm[B];

__device__ __forceinline__ unsigned long long ffma2(unsigned long long a,
                                                    unsigned long long b,
                                                    unsigned long long c) {
    unsigned long long d;
    asm("fma.rn.f32x2 %0, %1, %2, %3;" : "=l"(d) : "l"(a), "l"(b), "l"(c));
    return d;
}
__device__ __forceinline__ float hsum2(unsigned long long v) {
    float lo, hi;
    asm("mov.b64 {%0, %1}, %2;" : "=f"(lo), "=f"(hi) : "l"(v));
    return lo + hi;
}
__device__ __forceinline__ float sigmoidf(float x) { return 1.0f / (1.0f + __expf(-x)); }

__global__ void init_wm_kernel() {
    if (threadIdx.x < B) g_wm[threadIdx.x] = 0;
}

__global__ void __launch_bounds__(THREADS, 1) fused_kernel(
    const float* __restrict__ latent,  // (64,128)
    const float* __restrict__ W_hh,    // (384,128)
    const float* __restrict__ b_ih,    // (384,)
    const float* __restrict__ b_hh,    // (384,)
    const float* __restrict__ fc_W,    // (512,128)
    const float* __restrict__ fc_b,    // (512,)
    float* __restrict__ out)           // (64,2048,512)
{
    __shared__ __align__(16) float h_sm[H];
    __shared__ __align__(16) float r_sm[H];
    __shared__ __align__(16) float z_sm[H];
    __shared__ __align__(16) float gn_sm[H];
    __shared__ __align__(16) float hs_sm[32 * H];   // FC tile: 32 timesteps x 128

    const int tid = threadIdx.x;

    if (blockIdx.x < NREC) {
        // ================= Recurrence role: one batch element per CTA =================
        const int b = blockIdx.x;

        // Thread tid owns output index j = tid of gh; keep W_hh row j in registers.
        unsigned long long w[64];
        const unsigned long long* Wr =
            (const unsigned long long*)(W_hh + (size_t)tid * H);
        #pragma unroll
        for (int k = 0; k < 64; k++) w[k] = Wr[k];

        const float bhh = b_hh[tid];
        const float bi  = b_ih[tid];       // b_ir / b_iz / b_in depending on group
        const int grp = tid >> 7;          // 0:r 1:z 2:n
        const int li  = tid & 127;

        float b_in_i = 0.0f;
        if (tid < H) {
            b_in_i = b_ih[2 * H + tid];
            h_sm[tid] = latent[(size_t)b * H + tid];
        }
        __syncthreads();

        for (int t = 0; t < SEQ; t++) {
            // ---- gh[j] = dot(W_row_j, h) via packed f32x2 FMAs ----
            const ulonglong2* h2 = (const ulonglong2*)h_sm;
            unsigned long long a0 = 0ull, a1 = 0ull, a2 = 0ull, a3 = 0ull;
            #pragma unroll
            for (int k = 0; k < 32; k += 2) {
                ulonglong2 hv0 = h2[k];
                ulonglong2 hv1 = h2[k + 1];
                a0 = ffma2(w[2 * k    ], hv0.x, a0);
                a1 = ffma2(w[2 * k + 1], hv0.y, a1);
                a2 = ffma2(w[2 * k + 2], hv1.x, a2);
                a3 = ffma2(w[2 * k + 3], hv1.y, a3);
            }
            float g = hsum2(a0) + hsum2(a1) + hsum2(a2) + hsum2(a3) + bhh;

            // Pre-apply gate nonlinearities in parallel (r,z here; n needs r -> phase 2)
            if (grp == 0)      r_sm[li]  = sigmoidf(bi + g);
            else if (grp == 1) z_sm[li]  = sigmoidf(bi + g);
            else               gn_sm[li] = g;
            __syncthreads();

            if (tid < H) {
                float hold = h_sm[tid];
                float n  = tanhf(b_in_i + r_sm[tid] * gn_sm[tid]);
                float z  = z_sm[tid];
                float hn = (1.0f - z) * n + z * hold;
                h_sm[tid] = hn;
                g_hs[((size_t)b * SEQ + t) * H + tid] = hn;
            }
            __syncthreads();

            // Publish progress every 32 steps (FC consumes 32-row tiles)
            if ((t & 31) == 31 && tid == 0) {
                __threadfence();
                atomicExch(&g_wm[b], t + 1);
            }
        }
    } else {
        // ================= FC role: consume hs tiles as they are produced =================
        const int fcid = blockIdx.x - NREC;  // 0..83
        const int cb   = fcid / 21;          // fixed 128-col block -> fc_W stays in regs
        const int sub  = fcid % 21;
        const int col  = cb * H + (tid & 127);
        const int grp  = tid >> 7;           // 3 row-groups over the 32-row tile

        unsigned long long w[64];
        const unsigned long long* Wr =
            (const unsigned long long*)(fc_W + (size_t)col * H);
        #pragma unroll
        for (int k = 0; k < 64; k++) w[k] = Wr[k];
        const float bias = fc_b[col];

        // Tiles ordered by (tblk, b): 64 tblks x 64 batches, strided by 21 CTAs
        for (int ent = sub; ent < 64 * B; ent += 21) {
            const int tblk = ent >> 6;
            const int bb   = ent & 63;

            if (tid == 0) {
                const int need = (tblk + 1) * 32;
                while (atomicAdd(&g_wm[bb], 0) < need) __nanosleep(256);
            }
            __syncthreads();

            // Stage 32x128 fp32 hs tile (16 KB), coalesced float4
            const float4* src =
                (const float4*)(g_hs + ((size_t)bb * SEQ + (size_t)tblk * 32) * H);
            float4* dst = (float4*)hs_sm;
            #pragma unroll
            for (int it = 0; it < 3; it++) {
                int idx = tid + it * THREADS;
                if (idx < 1024) dst[idx] = src[idx];
            }
            __syncthreads();

            for (int r = grp; r < 32; r += 3) {
                const ulonglong2* hrow = (const ulonglong2*)(hs_sm + r * H);
                unsigned long long a0 = 0ull, a1 = 0ull;
                #pragma unroll
                for (int k = 0; k < 32; k++) {
                    ulonglong2 hv = hrow[k];
                    a0 = ffma2(w[2 * k    ], hv.x, a0);
                    a1 = ffma2(w[2 * k + 1], hv.y, a1);
                }
                out[((size_t)bb * SEQ + (size_t)tblk * 32 + r) * OUTF + col] =
                    hsum2(a0) + hsum2(a1) + bias;
            }
            __syncthreads();  // protect hs_sm before next tile's staging
        }
    }
}

extern "C" void kernel_launch(void* const* d_in, const int* in_sizes, int n_in,
                              void* d_out, int out_size) {
    const float* latent = (const float*)d_in[0];
    const float* W_hh   = (const float*)d_in[1];
    const float* b_ih   = (const float*)d_in[2];
    const float* b_hh   = (const float*)d_in[3];
    const float* fc_W   = (const float*)d_in[4];
    const float* fc_b   = (const float*)d_in[5];
    float* out = (float*)d_out;

    init_wm_kernel<<<1, 64>>>();
    fused_kernel<<<NREC + NFC, THREADS>>>(latent, W_hh, b_ih, b_hh, fc_W, fc_b, out);
}

// round 2
// speedup vs baseline: 1.0459x; 1.0459x over previous
#include <cuda_runtime.h>

#define SEQ   2048
#define H     128
#define B     64
#define OUTF  512
#define NREC  64
#define NFC   84        // 4 col-blocks x 21 CTAs; grid = 148 (wave-1 co-resident, no deadlock)
#define THREADS 384

// Scratch: hidden-state history + per-batch progress watermark (device globals; no allocs)
__device__ float g_hs[(size_t)B * SEQ * H];
__device__ int   g_wm[B];

__device__ __forceinline__ unsigned long long ffma2(unsigned long long a,
                                                    unsigned long long b,
                                                    unsigned long long c) {
    unsigned long long d;
    asm("fma.rn.f32x2 %0, %1, %2, %3;" : "=l"(d) : "l"(a), "l"(b), "l"(c));
    return d;
}
__device__ __forceinline__ unsigned long long add2(unsigned long long a,
                                                   unsigned long long b) {
    unsigned long long d;
    asm("add.rn.f32x2 %0, %1, %2;" : "=l"(d) : "l"(a), "l"(b));
    return d;
}
__device__ __forceinline__ float hsum2(unsigned long long v) {
    float lo, hi;
    asm("mov.b64 {%0, %1}, %2;" : "=f"(lo), "=f"(hi) : "l"(v));
    return lo + hi;
}
__device__ __forceinline__ float ex2f(float x) {
    float y; asm("ex2.approx.f32 %0, %1;" : "=f"(y) : "f"(x)); return y;
}
__device__ __forceinline__ float rcpf(float x) {
    float y; asm("rcp.approx.f32 %0, %1;" : "=f"(y) : "f"(x)); return y;
}
// sigmoid(x) = 1 / (1 + 2^(-x*log2e))
__device__ __forceinline__ float fast_sigmoid(float x) {
    return rcpf(1.0f + ex2f(-1.4426950408889634f * x));
}
// tanh(x) = 1 - 2 / (2^(2x*log2e) + 1); saturates correctly for |x| large
__device__ __forceinline__ float fast_tanh(float x) {
    float e = ex2f(2.8853900817779268f * x);
    return 1.0f - 2.0f * rcpf(e + 1.0f);
}

__global__ void init_wm_kernel() {
    if (threadIdx.x < B) g_wm[threadIdx.x] = 0;
}

__global__ void __launch_bounds__(THREADS, 1) fused_kernel(
    const float* __restrict__ latent,  // (64,128)
    const float* __restrict__ W_hh,    // (384,128)
    const float* __restrict__ b_ih,    // (384,)
    const float* __restrict__ b_hh,    // (384,)
    const float* __restrict__ fc_W,    // (512,128)
    const float* __restrict__ fc_b,    // (512,)
    float* __restrict__ out)           // (64,2048,512)
{
    __shared__ __align__(16) float h_sm[H];
    __shared__ __align__(16) float r_sm[H];
    __shared__ __align__(16) float z_sm[H];
    __shared__ __align__(16) float hs_sm[32 * H];   // FC tile: 32 timesteps x 128

    const int tid = threadIdx.x;

    if (blockIdx.x < NREC) {
        // ================= Recurrence role: one batch element per CTA =================
        const int b = blockIdx.x;

        // Thread tid owns gate-row j = tid of gh; W_hh row j lives in registers.
        unsigned long long w[64];
        const unsigned long long* Wr =
            (const unsigned long long*)(W_hh + (size_t)tid * H);
        #pragma unroll
        for (int k = 0; k < 64; k++) w[k] = Wr[k];

        const float bhh = b_hh[tid];
        const float bi  = b_ih[tid];       // b_ir / b_iz / b_in depending on group
        const int grp = tid >> 7;          // 0:r 1:z 2:n
        const int li  = tid & 127;

        if (tid < H) h_sm[tid] = latent[(size_t)b * H + tid];
        __syncthreads();

        float* g_hs_b = g_hs + (size_t)b * SEQ * H + li;

        for (int t = 0; t < SEQ; t++) {
            // ---- gh[j] = dot(W_row_j, h) via packed f32x2 FMAs ----
            const ulonglong2* h2 = (const ulonglong2*)h_sm;
            unsigned long long a0 = 0ull, a1 = 0ull, a2 = 0ull, a3 = 0ull;
            #pragma unroll
            for (int k = 0; k < 32; k += 2) {
                ulonglong2 hv0 = h2[k];
                ulonglong2 hv1 = h2[k + 1];
                a0 = ffma2(w[2 * k    ], hv0.x, a0);
                a1 = ffma2(w[2 * k + 1], hv0.y, a1);
                a2 = ffma2(w[2 * k + 2], hv1.x, a2);
                a3 = ffma2(w[2 * k + 3], hv1.y, a3);
            }
            a0 = add2(a0, a1);
            a2 = add2(a2, a3);
            a0 = add2(a0, a2);
            float g = hsum2(a0) + bhh;

            // r,z producers apply sigmoid in parallel; n-producer keeps raw g in reg
            if (grp == 0)      r_sm[li] = fast_sigmoid(bi + g);
            else if (grp == 1) z_sm[li] = fast_sigmoid(bi + g);
            __syncthreads();

            if (grp == 2) {
                float r    = r_sm[li];
                float z    = z_sm[li];
                float hold = h_sm[li];
                float n    = fast_tanh(fmaf(r, g, bi));
                float hn   = fmaf(z, hold - n, n);     // (1-z)*n + z*h
                h_sm[li]   = hn;
                g_hs_b[(size_t)t * H] = hn;
            }
            __syncthreads();

            // Publish progress every 32 steps (FC consumes 32-row tiles)
            if ((t & 31) == 31 && tid == 256) {
                __threadfence();
                atomicExch(&g_wm[b], t + 1);
            }
        }
    } else {
        // ================= FC role: consume hs tiles as they are produced =================
        const int fcid = blockIdx.x - NREC;  // 0..83
        const int cb   = fcid / 21;          // fixed 128-col block -> fc_W stays in regs
        const int sub  = fcid % 21;
        const int col  = cb * H + (tid & 127);
        const int grp  = tid >> 7;           // 3 row-groups over the 32-row tile

        unsigned long long w[64];
        const unsigned long long* Wr =
            (const unsigned long long*)(fc_W + (size_t)col * H);
        #pragma unroll
        for (int k = 0; k < 64; k++) w[k] = Wr[k];
        const float bias = fc_b[col];

        // Tiles ordered by (tblk, b): 64 tblks x 64 batches, strided by 21 CTAs
        for (int ent = sub; ent < 64 * B; ent += 21) {
            const int tblk = ent >> 6;
            const int bb   = ent & 63;

            if (tid == 0) {
                const int need = (tblk + 1) * 32;
                while (atomicAdd(&g_wm[bb], 0) < need) __nanosleep(256);
            }
            __syncthreads();

            // Stage 32x128 fp32 hs tile (16 KB), coalesced float4
            const float4* src =
                (const float4*)(g_hs + ((size_t)bb * SEQ + (size_t)tblk * 32) * H);
            float4* dst = (float4*)hs_sm;
            #pragma unroll
            for (int it = 0; it < 3; it++) {
                int idx = tid + it * THREADS;
                if (idx < 1024) dst[idx] = src[idx];
            }
            __syncthreads();

            for (int r = grp; r < 32; r += 3) {
                const ulonglong2* hrow = (const ulonglong2*)(hs_sm + r * H);
                unsigned long long a0 = 0ull, a1 = 0ull;
                #pragma unroll
                for (int k = 0; k < 32; k++) {
                    ulonglong2 hv = hrow[k];
                    a0 = ffma2(w[2 * k    ], hv.x, a0);
                    a1 = ffma2(w[2 * k + 1], hv.y, a1);
                }
                out[((size_t)bb * SEQ + (size_t)tblk * 32 + r) * OUTF + col] =
                    hsum2(a0) + hsum2(a1) + bias;
            }
            __syncthreads();  // protect hs_sm before next tile's staging
        }
    }
}

extern "C" void kernel_launch(void* const* d_in, const int* in_sizes, int n_in,
                              void* d_out, int out_size) {
    const float* latent = (const float*)d_in[0];
    const float* W_hh   = (const float*)d_in[1];
    const float* b_ih   = (const float*)d_in[2];
    const float* b_hh   = (const float*)d_in[3];
    const float* fc_W   = (const float*)d_in[4];
    const float* fc_b   = (const float*)d_in[5];
    float* out = (float*)d_out;

    init_wm_kernel<<<1, 64>>>();
    fused_kernel<<<NREC + NFC, THREADS>>>(latent, W_hh, b_ih, b_hh, fc_W, fc_b, out);
}